// round 2
// baseline (speedup 1.0000x reference)
#include <cuda_runtime.h>
#include <cuda_bf16.h>
#include <cstdint>

// MQIF neuron scan, round 2:
//  - expanded-FMA recurrence (12-cycle dependent chain)
//  - outputs staged in SMEM, streamed to GMEM by a dedicated DMA warp via
//    per-lane cp.async.bulk (removes STG issue cost from compute warps)
//  - input register double-buffered LDG.cs
//
// Layout: 128 CTAs x 96 threads. Threads 0..63 = compute (one chain each,
// 64 consecutive features of one batch). Threads 64..95 = DMA warp
// (lane j handles time-row j of each 32-step chunk).

#define STEPS  4096
#define FEAT   512
#define CHUNK  32
#define NCHUNK (STEPS / CHUNK)

__device__ __forceinline__ uint32_t smem_u32(const void* p) {
    return (uint32_t)__cvta_generic_to_shared(p);
}

__global__ __launch_bounds__(96, 1)
void mqif_scan_kernel(const float* __restrict__ in,
                      float* __restrict__ vout,
                      float* __restrict__ sout)
{
    // Double-buffered output staging: [buf][time-row][feature-lane]
    __shared__ __align__(256) float vbuf[2][CHUNK][64];
    __shared__ __align__(256) float sbuf[2][CHUNK][64];

    const int b  = blockIdx.x >> 3;         // batch index (16)
    const int f0 = (blockIdx.x & 7) * 64;   // feature-group base (8 groups)

    if (threadIdx.x < 64) {
        // ───────────── compute warps ─────────────
        const int ct = threadIdx.x;
        const int f  = f0 + ct;

        const float* ip = in + ((size_t)b * STEPS) * FEAT + f;

        float v = -60.0f;   // vr
        float u = 0.0f;

        // Prime input double buffer.
        float buf[CHUNK];
#pragma unroll
        for (int j = 0; j < CHUNK; j++)
            buf[j] = __ldcs(ip + j * FEAT);

        for (int chunk = 0; chunk < NCHUNK; chunk++) {
            // Prefetch next chunk of input.
            float nbuf[CHUNK];
            const float* ipn = ip + CHUNK * FEAT;
            const bool more = (chunk + 1) < NCHUNK;
#pragma unroll
            for (int j = 0; j < CHUNK; j++)
                nbuf[j] = more ? __ldcs(ipn + j * FEAT) : 0.0f;

            const int bs = chunk & 1;
#pragma unroll
            for (int j = 0; j < CHUNK; j++) {
                const float I = buf[j];
                const bool fired = (v >= 30.0f);             // v_peak

                // visible voltage + spike for this step
                vbuf[bs][j][ct] = fired ? 30.0f : v;
                sbuf[bs][j][ct] = fired ? 1.0f : 0.0f;

                // v' = 2e-4 v^2 + 1.02 v + (0.48 + 0.005(I - u))
                const float c  = fmaf(0.005f, I - u, 0.48f);
                const float t1 = fmaf(2.0e-4f, v, 1.02f);
                const float vc = fmaf(t1, v, c);
                // u' = 0.9995 u + 1e-4 v + 0.006
                const float ua = fmaf(1.0e-4f, v, 0.006f);
                const float uc = fmaf(0.9995f, u, ua);

                v = fired ? -60.0f : vc;                     // v_reset
                u = fired ? (u + 2.0f) : uc;                 // u + d
            }

#pragma unroll
            for (int j = 0; j < CHUNK; j++) buf[j] = nbuf[j];
            ip = ipn;

            // Make STS visible to the async proxy, then hand off to DMA warp.
            asm volatile("fence.proxy.async.shared::cta;" ::: "memory");
            __syncthreads();   // B(chunk)
        }

        // Trailing entry t = STEPS: raw final v, spike on raw v.
        float* vpe = vout + ((size_t)b * (STEPS + 1) + STEPS) * FEAT + f;
        float* spe = sout + ((size_t)b * (STEPS + 1) + STEPS) * FEAT + f;
        __stcs(vpe, v);
        __stcs(spe, (v >= 30.0f) ? 1.0f : 0.0f);
    } else {
        // ───────────── DMA warp ─────────────
        const int lane = threadIdx.x - 64;   // 0..31 -> time-row within chunk

        // gmem row pointers for this lane's time row of chunk 0
        float* vdst = vout + ((size_t)b * (STEPS + 1) + lane) * FEAT + f0;
        float* sdst = sout + ((size_t)b * (STEPS + 1) + lane) * FEAT + f0;

        for (int chunk = 0; chunk < NCHUNK; chunk++) {
            __syncthreads();   // B(chunk): staging buffer chunk&1 is full

            const int bs = chunk & 1;
            const uint32_t vsrc = smem_u32(&vbuf[bs][lane][0]);
            const uint32_t ssrc = smem_u32(&sbuf[bs][lane][0]);

            asm volatile(
                "cp.async.bulk.global.shared::cta.bulk_group [%0], [%1], 256;"
                :: "l"(vdst), "r"(vsrc) : "memory");
            asm volatile(
                "cp.async.bulk.global.shared::cta.bulk_group [%0], [%1], 256;"
                :: "l"(sdst), "r"(ssrc) : "memory");
            asm volatile("cp.async.bulk.commit_group;" ::: "memory");
            // Drain smem reads of this group before compute reuses the buffer
            // (compute rewrites buffer bs only after the NEXT barrier).
            asm volatile("cp.async.bulk.wait_group.read 0;" ::: "memory");

            vdst += (size_t)CHUNK * FEAT;
            sdst += (size_t)CHUNK * FEAT;
        }
        // Ensure all bulk stores are globally complete before kernel exit.
        asm volatile("cp.async.bulk.wait_group 0;" ::: "memory");
    }
}

extern "C" void kernel_launch(void* const* d_in, const int* in_sizes, int n_in,
                              void* d_out, int out_size)
{
    const float* in = (const float*)d_in[0];
    float* out = (float*)d_out;
    const size_t half = (size_t)16 * (STEPS + 1) * FEAT;
    float* vout = out;
    float* sout = out + half;

    mqif_scan_kernel<<<128, 96>>>(in, vout, sout);
}